// round 7
// baseline (speedup 1.0000x reference)
#include <cuda_runtime.h>
#include <cuda_bf16.h>
#include <cstdint>

#define VOCAB 50257
#define EMB   16
#define BS    8
#define MCW   512
#define NROW  (BS * MCW)   // 4096
#define NCHUNK 8           // attnout p-chunks
#define CHUNK  (MCW / NCHUNK)  // 64
typedef unsigned long long ull;

// ---------------- scratch (static device globals; no allocs) ----------------
__device__ float g_q[NROW * EMB];
__device__ float g_k[NROW * EMB];
__device__ float g_v[NROW * EMB];
__device__ float g_sc[BS * MCW * MCW];          // TRANSPOSED probs: [b][k][q] (8 MB)
__device__ float g_part[NCHUNK * EMB * NROW];   // attnout partials: [chunk][e][r]

__device__ __forceinline__ ull pack2(float lo, float hi) {
    ull r;
    asm("mov.b64 %0, {%1, %2};" : "=l"(r) : "f"(lo), "f"(hi));
    return r;
}
__device__ __forceinline__ void unpack2(ull p, float& lo, float& hi) {
    asm("mov.b64 {%0, %1}, %2;" : "=f"(lo), "=f"(hi) : "l"(p));
}

// ---------------- Kernel A: embeddings -> Q, K, V ----------------
__global__ void qkv_kernel(const int* __restrict__ x,
                           const float* __restrict__ emb_table,
                           const float* __restrict__ Wq, const float* __restrict__ bq,
                           const float* __restrict__ Wk, const float* __restrict__ bk,
                           const float* __restrict__ Wv, const float* __restrict__ bv) {
    __shared__ float sWq[EMB * EMB], sWk[EMB * EMB], sWv[EMB * EMB];
    __shared__ float sbq[EMB], sbk[EMB], sbv[EMB];
    int tid = threadIdx.x;
    if (tid < EMB * EMB) { sWq[tid] = Wq[tid]; sWk[tid] = Wk[tid]; sWv[tid] = Wv[tid]; }
    if (tid < EMB)       { sbq[tid] = bq[tid]; sbk[tid] = bk[tid]; sbv[tid] = bv[tid]; }
    __syncthreads();

    int t = blockIdx.x * blockDim.x + tid;
    if (t >= NROW) return;
    int tok = x[t];

    float emb[EMB];
    const float4* ep = reinterpret_cast<const float4*>(emb_table + (size_t)tok * EMB);
#pragma unroll
    for (int i = 0; i < 4; i++) {
        float4 v4 = ep[i];
        emb[4 * i + 0] = v4.x; emb[4 * i + 1] = v4.y;
        emb[4 * i + 2] = v4.z; emb[4 * i + 3] = v4.w;
    }

#pragma unroll
    for (int i = 0; i < EMB; i++) {
        float aq = sbq[i], ak = sbk[i], av = sbv[i];
#pragma unroll
        for (int e = 0; e < EMB; e++) {
            aq += emb[e] * sWq[i * EMB + e];
            ak += emb[e] * sWk[i * EMB + e];
            av += emb[e] * sWv[i * EMB + e];
        }
        g_q[t * EMB + i] = aq;
        g_k[t * EMB + i] = ak;
        g_v[t * EMB + i] = av;
    }
}

// ---------------- Kernel B: fused scores + mask + zero->-inf + softmax(q) ----------------
#define QPAD 20
__global__ __launch_bounds__(256) void scorexmax_kernel() {
    __shared__ float sQ[MCW * QPAD];   // [q][20] padded, 40 KB
    int b = blockIdx.y;
    int kbase = blockIdx.x * 8;
    int tid = threadIdx.x;
    int warp = tid >> 5, lane = tid & 31;

    for (int i = tid; i < MCW * 4; i += 256) {
        int q = i >> 2, e4 = i & 3;
        float4 v4 = *reinterpret_cast<const float4*>(g_q + ((size_t)(b * MCW + q)) * EMB + e4 * 4);
        *reinterpret_cast<float4*>(sQ + q * QPAD + e4 * 4) = v4;
    }
    __syncthreads();

    int k = kbase + warp;
    float krow[EMB];
    const float4* kp = reinterpret_cast<const float4*>(g_k + ((size_t)(b * MCW + k)) * EMB);
#pragma unroll
    for (int i = 0; i < 4; i++) {
        float4 v4 = kp[i];
        krow[4 * i + 0] = v4.x; krow[4 * i + 1] = v4.y;
        krow[4 * i + 2] = v4.z; krow[4 * i + 3] = v4.w;
    }

    float* prow = g_sc + (size_t)b * MCW * MCW + (size_t)k * MCW;
    const float NEG_INF = __int_as_float(0xff800000);

    float v[16];
    bool live[16];
#pragma unroll
    for (int j = 0; j < 16; j++) {
        int q = j * 32 + lane;
        if (j * 32 + 31 < k) {            // chunk entirely masked: prob = 0 exactly
            live[j] = false;
            v[j] = NEG_INF;
            prow[q] = 0.0f;
        } else {
            live[j] = true;
            float dot = 0.f;
#pragma unroll
            for (int e4 = 0; e4 < 4; e4++) {
                float4 a = *reinterpret_cast<const float4*>(sQ + q * QPAD + e4 * 4);
                dot += a.x * krow[4 * e4 + 0] + a.y * krow[4 * e4 + 1]
                     + a.z * krow[4 * e4 + 2] + a.w * krow[4 * e4 + 3];
            }
            float val = (q >= k) ? dot : 0.0f;
            if (val == 0.0f) val = NEG_INF;
            v[j] = val;
        }
    }

    float mx = NEG_INF;
#pragma unroll
    for (int j = 0; j < 16; j++) mx = fmaxf(mx, v[j]);
#pragma unroll
    for (int s = 16; s > 0; s >>= 1) mx = fmaxf(mx, __shfl_xor_sync(0xffffffffu, mx, s));

    float sum = 0.f;
#pragma unroll
    for (int j = 0; j < 16; j++) {
        if (live[j]) { v[j] = expf(v[j] - mx); sum += v[j]; }
    }
#pragma unroll
    for (int s = 16; s > 0; s >>= 1) sum += __shfl_xor_sync(0xffffffffu, sum, s);

    float inv = 1.0f / sum;
#pragma unroll
    for (int j = 0; j < 16; j++) {
        if (live[j]) prow[j * 32 + lane] = v[j] * inv;
    }
}

// ---------------- Kernel C: attnout partials, 8 p-chunks, triangular skip ----------------
__global__ void attnout_kernel() {
    int b = blockIdx.y;
    int w0 = blockIdx.x * 32;
    int c  = blockIdx.z;
    int wl = threadIdx.x, pg = threadIdx.y;

    if (c * CHUNK > w0 + 31) {           // prob exactly 0 here: write zeros, done
        if (pg == 0) {
#pragma unroll
            for (int e = 0; e < EMB; e++)
                g_part[(size_t)c * EMB * NROW + (size_t)e * NROW + b * MCW + w0 + wl] = 0.f;
        }
        return;
    }

    __shared__ float sV[CHUNK * EMB];    // 4 KB
    __shared__ float red[256 * EMB];     // 16 KB
    int tid = pg * 32 + wl;

    for (int i = tid; i < CHUNK * EMB; i += 256)
        sV[i] = g_v[(size_t)b * MCW * EMB + c * CHUNK * EMB + i];
    __syncthreads();

    float acc[EMB];
#pragma unroll
    for (int e = 0; e < EMB; e++) acc[e] = 0.f;

    const float* wbase = g_sc + (size_t)b * MCW * MCW + w0 + wl;
#pragma unroll
    for (int pi = 0; pi < CHUNK / 8; pi++) {
        int pl = pi * 8 + pg;
        float wgt = wbase[(size_t)(c * CHUNK + pl) * MCW];
#pragma unroll
        for (int e = 0; e < EMB; e++) acc[e] += wgt * sV[pl * EMB + e];
    }

#pragma unroll
    for (int e = 0; e < EMB; e++) red[tid * EMB + e] = acc[e];
    __syncthreads();

    if (pg == 0) {
#pragma unroll
        for (int e = 0; e < EMB; e++) {
            float s = 0.f;
#pragma unroll
            for (int g = 0; g < 8; g++) s += red[(g * 32 + wl) * EMB + e];
            g_part[(size_t)c * EMB * NROW + (size_t)e * NROW + b * MCW + w0 + wl] = s;
        }
    }
}

// ---------------- Kernel D: logits = out @ Wl.T + bl  (823 MB write) ----------------
// k=2 vocab/thread @ 128 threads, __launch_bounds__(128, 4): ~105 regs ->
// 4 blocks/SM = 16 warps/SM = 4 warps/SMSP (2x R5/R6 latency hiding).
// Each block covers 256 vocab; grid.x = ceil(VOCAB/256) = 197.
#define E_RT 128
__global__ __launch_bounds__(128, 4) void logits_kernel(const float* __restrict__ Wl,
                                                        const float* __restrict__ bl,
                                                        float* __restrict__ out) {
    __shared__ float s[EMB * E_RT];   // s[e][r_local], 8 KB
    int tid = threadIdx.x;
    int rbase = blockIdx.y * E_RT;

    // stage s tile = sum of the 8 attnout partial planes (fixed trip count)
    for (int i = tid; i < EMB * E_RT; i += 128) {
        int e = i >> 7, rl = i & (E_RT - 1);
        int idx = e * NROW + rbase + rl;
        float a = 0.f;
#pragma unroll
        for (int c = 0; c < NCHUNK; c++)
            a += g_part[c * (EMB * NROW) + idx];
        s[i] = a;
    }

    int v0 = blockIdx.x * 256 + tid;
    int v1 = v0 + 128;
    bool ok0 = (v0 < VOCAB), ok1 = (v1 < VOCAB);
    ull w0[EMB], w1[EMB], b0 = 0ull, b1 = 0ull;
    if (ok0) {
        const float4* wp = reinterpret_cast<const float4*>(Wl + (size_t)v0 * EMB);
#pragma unroll
        for (int i = 0; i < 4; i++) {
            float4 q = wp[i];
            w0[4 * i + 0] = pack2(q.x, q.x); w0[4 * i + 1] = pack2(q.y, q.y);
            w0[4 * i + 2] = pack2(q.z, q.z); w0[4 * i + 3] = pack2(q.w, q.w);
        }
        float bb = bl[v0]; b0 = pack2(bb, bb);
    } else {
#pragma unroll
        for (int e = 0; e < EMB; e++) w0[e] = 0ull;
    }
    if (ok1) {
        const float4* wp = reinterpret_cast<const float4*>(Wl + (size_t)v1 * EMB);
#pragma unroll
        for (int i = 0; i < 4; i++) {
            float4 q = wp[i];
            w1[4 * i + 0] = pack2(q.x, q.x); w1[4 * i + 1] = pack2(q.y, q.y);
            w1[4 * i + 2] = pack2(q.z, q.z); w1[4 * i + 3] = pack2(q.w, q.w);
        }
        float bb = bl[v1]; b1 = pack2(bb, bb);
    } else {
#pragma unroll
        for (int e = 0; e < EMB; e++) w1[e] = 0ull;
    }
    __syncthreads();

#pragma unroll 2
    for (int rp = 0; rp < E_RT / 2; rp++) {
        ull acc0 = b0, acc1 = b1;
#pragma unroll
        for (int e = 0; e < EMB; e++) {
            ull o = *reinterpret_cast<const ull*>(s + e * E_RT + 2 * rp);
            asm("fma.rn.f32x2 %0, %1, %2, %0;" : "+l"(acc0) : "l"(o), "l"(w0[e]));
            asm("fma.rn.f32x2 %0, %1, %2, %0;" : "+l"(acc1) : "l"(o), "l"(w1[e]));
        }
        int r = rbase + 2 * rp;
        float lo, hi;
        if (ok0) {
            unpack2(acc0, lo, hi);
            __stcs(&out[(size_t)r * VOCAB + v0], lo);
            __stcs(&out[(size_t)(r + 1) * VOCAB + v0], hi);
        }
        if (ok1) {
            unpack2(acc1, lo, hi);
            __stcs(&out[(size_t)r * VOCAB + v1], lo);
            __stcs(&out[(size_t)(r + 1) * VOCAB + v1], hi);
        }
    }
}

// ---------------- launch ----------------
extern "C" void kernel_launch(void* const* d_in, const int* in_sizes, int n_in,
                              void* d_out, int out_size) {
    const int*   x   = (const int*)  d_in[0];
    const float* emb = (const float*)d_in[1];
    const float* Wq  = (const float*)d_in[2];
    const float* bq  = (const float*)d_in[3];
    const float* Wk  = (const float*)d_in[4];
    const float* bk  = (const float*)d_in[5];
    const float* Wv  = (const float*)d_in[6];
    const float* bv  = (const float*)d_in[7];
    const float* Wl  = (const float*)d_in[8];
    const float* bl  = (const float*)d_in[9];
    float* out = (float*)d_out;

    qkv_kernel<<<NROW / 256, 256>>>(x, emb, Wq, bq, Wk, bk, Wv, bv);

    dim3 gB(MCW / 8, BS);
    scorexmax_kernel<<<gB, 256>>>();

    dim3 gD(MCW / 32, BS, NCHUNK), bD(32, 8);
    attnout_kernel<<<gD, bD>>>();

    dim3 gE((VOCAB + 255) / 256, NROW / E_RT);
    logits_kernel<<<gE, 128>>>(Wl, bl, out);
}

// round 8
// speedup vs baseline: 1.0059x; 1.0059x over previous
#include <cuda_runtime.h>
#include <cuda_bf16.h>
#include <cstdint>

#define VOCAB 50257
#define EMB   16
#define BS    8
#define MCW   512
#define NROW  (BS * MCW)   // 4096
#define NCHUNK 8           // attnout p-chunks
#define CHUNK  (MCW / NCHUNK)  // 64
typedef unsigned long long ull;

// ---------------- scratch (static device globals; no allocs) ----------------
__device__ float g_q[NROW * EMB];
__device__ float g_k[NROW * EMB];
__device__ float g_v[NROW * EMB];
__device__ float g_sc[BS * MCW * MCW];          // TRANSPOSED probs: [b][k][q] (8 MB)
__device__ float g_part[NCHUNK * EMB * NROW];   // attnout partials: [chunk][e][r]

__device__ __forceinline__ ull pack2(float lo, float hi) {
    ull r;
    asm("mov.b64 %0, {%1, %2};" : "=l"(r) : "f"(lo), "f"(hi));
    return r;
}
__device__ __forceinline__ void unpack2(ull p, float& lo, float& hi) {
    asm("mov.b64 {%0, %1}, %2;" : "=f"(lo), "=f"(hi) : "l"(p));
}

// ---------------- Kernel A: embeddings -> Q, K, V ----------------
__global__ void qkv_kernel(const int* __restrict__ x,
                           const float* __restrict__ emb_table,
                           const float* __restrict__ Wq, const float* __restrict__ bq,
                           const float* __restrict__ Wk, const float* __restrict__ bk,
                           const float* __restrict__ Wv, const float* __restrict__ bv) {
    __shared__ float sWq[EMB * EMB], sWk[EMB * EMB], sWv[EMB * EMB];
    __shared__ float sbq[EMB], sbk[EMB], sbv[EMB];
    int tid = threadIdx.x;
    if (tid < EMB * EMB) { sWq[tid] = Wq[tid]; sWk[tid] = Wk[tid]; sWv[tid] = Wv[tid]; }
    if (tid < EMB)       { sbq[tid] = bq[tid]; sbk[tid] = bk[tid]; sbv[tid] = bv[tid]; }
    __syncthreads();

    int t = blockIdx.x * blockDim.x + tid;
    if (t >= NROW) return;
    int tok = x[t];

    float emb[EMB];
    const float4* ep = reinterpret_cast<const float4*>(emb_table + (size_t)tok * EMB);
#pragma unroll
    for (int i = 0; i < 4; i++) {
        float4 v4 = ep[i];
        emb[4 * i + 0] = v4.x; emb[4 * i + 1] = v4.y;
        emb[4 * i + 2] = v4.z; emb[4 * i + 3] = v4.w;
    }

#pragma unroll
    for (int i = 0; i < EMB; i++) {
        float aq = sbq[i], ak = sbk[i], av = sbv[i];
#pragma unroll
        for (int e = 0; e < EMB; e++) {
            aq += emb[e] * sWq[i * EMB + e];
            ak += emb[e] * sWk[i * EMB + e];
            av += emb[e] * sWv[i * EMB + e];
        }
        g_q[t * EMB + i] = aq;
        g_k[t * EMB + i] = ak;
        g_v[t * EMB + i] = av;
    }
}

// ---------------- Kernel B: fused scores + mask + zero->-inf + softmax(q) ----------------
#define QPAD 20
__global__ __launch_bounds__(256) void scorexmax_kernel() {
    __shared__ float sQ[MCW * QPAD];   // [q][20] padded, 40 KB
    int b = blockIdx.y;
    int kbase = blockIdx.x * 8;
    int tid = threadIdx.x;
    int warp = tid >> 5, lane = tid & 31;

    for (int i = tid; i < MCW * 4; i += 256) {
        int q = i >> 2, e4 = i & 3;
        float4 v4 = *reinterpret_cast<const float4*>(g_q + ((size_t)(b * MCW + q)) * EMB + e4 * 4);
        *reinterpret_cast<float4*>(sQ + q * QPAD + e4 * 4) = v4;
    }
    __syncthreads();

    int k = kbase + warp;
    float krow[EMB];
    const float4* kp = reinterpret_cast<const float4*>(g_k + ((size_t)(b * MCW + k)) * EMB);
#pragma unroll
    for (int i = 0; i < 4; i++) {
        float4 v4 = kp[i];
        krow[4 * i + 0] = v4.x; krow[4 * i + 1] = v4.y;
        krow[4 * i + 2] = v4.z; krow[4 * i + 3] = v4.w;
    }

    float* prow = g_sc + (size_t)b * MCW * MCW + (size_t)k * MCW;
    const float NEG_INF = __int_as_float(0xff800000);

    float v[16];
    bool live[16];
#pragma unroll
    for (int j = 0; j < 16; j++) {
        int q = j * 32 + lane;
        if (j * 32 + 31 < k) {            // chunk entirely masked: prob = 0 exactly
            live[j] = false;
            v[j] = NEG_INF;
            prow[q] = 0.0f;
        } else {
            live[j] = true;
            float dot = 0.f;
#pragma unroll
            for (int e4 = 0; e4 < 4; e4++) {
                float4 a = *reinterpret_cast<const float4*>(sQ + q * QPAD + e4 * 4);
                dot += a.x * krow[4 * e4 + 0] + a.y * krow[4 * e4 + 1]
                     + a.z * krow[4 * e4 + 2] + a.w * krow[4 * e4 + 3];
            }
            float val = (q >= k) ? dot : 0.0f;
            if (val == 0.0f) val = NEG_INF;
            v[j] = val;
        }
    }

    float mx = NEG_INF;
#pragma unroll
    for (int j = 0; j < 16; j++) mx = fmaxf(mx, v[j]);
#pragma unroll
    for (int s = 16; s > 0; s >>= 1) mx = fmaxf(mx, __shfl_xor_sync(0xffffffffu, mx, s));

    float sum = 0.f;
#pragma unroll
    for (int j = 0; j < 16; j++) {
        if (live[j]) { v[j] = expf(v[j] - mx); sum += v[j]; }
    }
#pragma unroll
    for (int s = 16; s > 0; s >>= 1) sum += __shfl_xor_sync(0xffffffffu, sum, s);

    float inv = 1.0f / sum;
#pragma unroll
    for (int j = 0; j < 16; j++) {
        if (live[j]) prow[j * 32 + lane] = v[j] * inv;
    }
}

// ---------------- Kernel C: attnout partials, 8 p-chunks, triangular skip ----------------
__global__ void attnout_kernel() {
    int b = blockIdx.y;
    int w0 = blockIdx.x * 32;
    int c  = blockIdx.z;
    int wl = threadIdx.x, pg = threadIdx.y;

    if (c * CHUNK > w0 + 31) {           // prob exactly 0 here: write zeros, done
        if (pg == 0) {
#pragma unroll
            for (int e = 0; e < EMB; e++)
                g_part[(size_t)c * EMB * NROW + (size_t)e * NROW + b * MCW + w0 + wl] = 0.f;
        }
        return;
    }

    __shared__ float sV[CHUNK * EMB];    // 4 KB
    __shared__ float red[256 * EMB];     // 16 KB
    int tid = pg * 32 + wl;

    for (int i = tid; i < CHUNK * EMB; i += 256)
        sV[i] = g_v[(size_t)b * MCW * EMB + c * CHUNK * EMB + i];
    __syncthreads();

    float acc[EMB];
#pragma unroll
    for (int e = 0; e < EMB; e++) acc[e] = 0.f;

    const float* wbase = g_sc + (size_t)b * MCW * MCW + w0 + wl;
#pragma unroll
    for (int pi = 0; pi < CHUNK / 8; pi++) {
        int pl = pi * 8 + pg;
        float wgt = wbase[(size_t)(c * CHUNK + pl) * MCW];
#pragma unroll
        for (int e = 0; e < EMB; e++) acc[e] += wgt * sV[pl * EMB + e];
    }

#pragma unroll
    for (int e = 0; e < EMB; e++) red[tid * EMB + e] = acc[e];
    __syncthreads();

    if (pg == 0) {
#pragma unroll
        for (int e = 0; e < EMB; e++) {
            float s = 0.f;
#pragma unroll
            for (int g = 0; g < 8; g++) s += red[(g * 32 + wl) * EMB + e];
            g_part[(size_t)c * EMB * NROW + (size_t)e * NROW + b * MCW + w0 + wl] = s;
        }
    }
}

// ---------------- Kernel D: logits = out @ Wl.T + bl  (823 MB write) ----------------
// k=2 vocab/thread @ 128 threads, __launch_bounds__(128, 4): ~105 regs ->
// 4 blocks/SM = 16 warps/SM = 4 warps/SMSP (2x R5/R6 latency hiding).
// Each block covers 256 vocab; grid.x = ceil(VOCAB/256) = 197.
#define E_RT 128
__global__ __launch_bounds__(128, 4) void logits_kernel(const float* __restrict__ Wl,
                                                        const float* __restrict__ bl,
                                                        float* __restrict__ out) {
    __shared__ float s[EMB * E_RT];   // s[e][r_local], 8 KB
    int tid = threadIdx.x;
    int rbase = blockIdx.y * E_RT;

    // stage s tile = sum of the 8 attnout partial planes (fixed trip count)
    for (int i = tid; i < EMB * E_RT; i += 128) {
        int e = i >> 7, rl = i & (E_RT - 1);
        int idx = e * NROW + rbase + rl;
        float a = 0.f;
#pragma unroll
        for (int c = 0; c < NCHUNK; c++)
            a += g_part[c * (EMB * NROW) + idx];
        s[i] = a;
    }

    int v0 = blockIdx.x * 256 + tid;
    int v1 = v0 + 128;
    bool ok0 = (v0 < VOCAB), ok1 = (v1 < VOCAB);
    ull w0[EMB], w1[EMB], b0 = 0ull, b1 = 0ull;
    if (ok0) {
        const float4* wp = reinterpret_cast<const float4*>(Wl + (size_t)v0 * EMB);
#pragma unroll
        for (int i = 0; i < 4; i++) {
            float4 q = wp[i];
            w0[4 * i + 0] = pack2(q.x, q.x); w0[4 * i + 1] = pack2(q.y, q.y);
            w0[4 * i + 2] = pack2(q.z, q.z); w0[4 * i + 3] = pack2(q.w, q.w);
        }
        float bb = bl[v0]; b0 = pack2(bb, bb);
    } else {
#pragma unroll
        for (int e = 0; e < EMB; e++) w0[e] = 0ull;
    }
    if (ok1) {
        const float4* wp = reinterpret_cast<const float4*>(Wl + (size_t)v1 * EMB);
#pragma unroll
        for (int i = 0; i < 4; i++) {
            float4 q = wp[i];
            w1[4 * i + 0] = pack2(q.x, q.x); w1[4 * i + 1] = pack2(q.y, q.y);
            w1[4 * i + 2] = pack2(q.z, q.z); w1[4 * i + 3] = pack2(q.w, q.w);
        }
        float bb = bl[v1]; b1 = pack2(bb, bb);
    } else {
#pragma unroll
        for (int e = 0; e < EMB; e++) w1[e] = 0ull;
    }
    __syncthreads();

#pragma unroll 2
    for (int rp = 0; rp < E_RT / 2; rp++) {
        ull acc0 = b0, acc1 = b1;
#pragma unroll
        for (int e = 0; e < EMB; e++) {
            ull o = *reinterpret_cast<const ull*>(s + e * E_RT + 2 * rp);
            asm("fma.rn.f32x2 %0, %1, %2, %0;" : "+l"(acc0) : "l"(o), "l"(w0[e]));
            asm("fma.rn.f32x2 %0, %1, %2, %0;" : "+l"(acc1) : "l"(o), "l"(w1[e]));
        }
        int r = rbase + 2 * rp;
        float lo, hi;
        if (ok0) {
            unpack2(acc0, lo, hi);
            __stcs(&out[(size_t)r * VOCAB + v0], lo);
            __stcs(&out[(size_t)(r + 1) * VOCAB + v0], hi);
        }
        if (ok1) {
            unpack2(acc1, lo, hi);
            __stcs(&out[(size_t)r * VOCAB + v1], lo);
            __stcs(&out[(size_t)(r + 1) * VOCAB + v1], hi);
        }
    }
}

// ---------------- launch ----------------
extern "C" void kernel_launch(void* const* d_in, const int* in_sizes, int n_in,
                              void* d_out, int out_size) {
    const int*   x   = (const int*)  d_in[0];
    const float* emb = (const float*)d_in[1];
    const float* Wq  = (const float*)d_in[2];
    const float* bq  = (const float*)d_in[3];
    const float* Wk  = (const float*)d_in[4];
    const float* bk  = (const float*)d_in[5];
    const float* Wv  = (const float*)d_in[6];
    const float* bv  = (const float*)d_in[7];
    const float* Wl  = (const float*)d_in[8];
    const float* bl  = (const float*)d_in[9];
    float* out = (float*)d_out;

    qkv_kernel<<<NROW / 256, 256>>>(x, emb, Wq, bq, Wk, bk, Wv, bv);

    dim3 gB(MCW / 8, BS);
    scorexmax_kernel<<<gB, 256>>>();

    dim3 gD(MCW / 32, BS, NCHUNK), bD(32, 8);
    attnout_kernel<<<gD, bD>>>();

    dim3 gE((VOCAB + 255) / 256, NROW / E_RT);
    logits_kernel<<<gE, 128>>>(Wl, bl, out);
}

// round 9
// speedup vs baseline: 1.3081x; 1.3004x over previous
#include <cuda_runtime.h>
#include <cuda_bf16.h>
#include <cstdint>

#define VOCAB 50257
#define EMB   16
#define BS    8
#define MCW   512
#define NROW  (BS * MCW)   // 4096
#define NCHUNK 8           // attnout p-chunks
#define CHUNK  (MCW / NCHUNK)  // 64
typedef unsigned long long ull;

// ---------------- scratch (static device globals; no allocs) ----------------
__device__ float g_q[NROW * EMB];
__device__ float g_k[NROW * EMB];
__device__ float g_v[NROW * EMB];
__device__ float g_sc[BS * MCW * MCW];          // TRANSPOSED probs: [b][k][q] (8 MB)
__device__ float g_part[NCHUNK * EMB * NROW];   // attnout partials: [chunk][e][r]

__device__ __forceinline__ ull pack2(float lo, float hi) {
    ull r;
    asm("mov.b64 %0, {%1, %2};" : "=l"(r) : "f"(lo), "f"(hi));
    return r;
}
__device__ __forceinline__ void unpack2(ull p, float& lo, float& hi) {
    asm("mov.b64 {%0, %1}, %2;" : "=f"(lo), "=f"(hi) : "l"(p));
}

// ---------------- Kernel A: embeddings -> Q, K, V ----------------
__global__ void qkv_kernel(const int* __restrict__ x,
                           const float* __restrict__ emb_table,
                           const float* __restrict__ Wq, const float* __restrict__ bq,
                           const float* __restrict__ Wk, const float* __restrict__ bk,
                           const float* __restrict__ Wv, const float* __restrict__ bv) {
    __shared__ float sWq[EMB * EMB], sWk[EMB * EMB], sWv[EMB * EMB];
    __shared__ float sbq[EMB], sbk[EMB], sbv[EMB];
    int tid = threadIdx.x;
    if (tid < EMB * EMB) { sWq[tid] = Wq[tid]; sWk[tid] = Wk[tid]; sWv[tid] = Wv[tid]; }
    if (tid < EMB)       { sbq[tid] = bq[tid]; sbk[tid] = bk[tid]; sbv[tid] = bv[tid]; }
    __syncthreads();

    int t = blockIdx.x * blockDim.x + tid;
    if (t >= NROW) return;
    int tok = x[t];

    float emb[EMB];
    const float4* ep = reinterpret_cast<const float4*>(emb_table + (size_t)tok * EMB);
#pragma unroll
    for (int i = 0; i < 4; i++) {
        float4 v4 = ep[i];
        emb[4 * i + 0] = v4.x; emb[4 * i + 1] = v4.y;
        emb[4 * i + 2] = v4.z; emb[4 * i + 3] = v4.w;
    }

#pragma unroll
    for (int i = 0; i < EMB; i++) {
        float aq = sbq[i], ak = sbk[i], av = sbv[i];
#pragma unroll
        for (int e = 0; e < EMB; e++) {
            aq += emb[e] * sWq[i * EMB + e];
            ak += emb[e] * sWk[i * EMB + e];
            av += emb[e] * sWv[i * EMB + e];
        }
        g_q[t * EMB + i] = aq;
        g_k[t * EMB + i] = ak;
        g_v[t * EMB + i] = av;
    }
}

// ---------------- Kernel B: fused scores + mask + zero->-inf + softmax(q) ----------------
#define QPAD 20
__global__ __launch_bounds__(256) void scorexmax_kernel() {
    __shared__ float sQ[MCW * QPAD];   // [q][20] padded, 40 KB
    int b = blockIdx.y;
    int kbase = blockIdx.x * 8;
    int tid = threadIdx.x;
    int warp = tid >> 5, lane = tid & 31;

    for (int i = tid; i < MCW * 4; i += 256) {
        int q = i >> 2, e4 = i & 3;
        float4 v4 = *reinterpret_cast<const float4*>(g_q + ((size_t)(b * MCW + q)) * EMB + e4 * 4);
        *reinterpret_cast<float4*>(sQ + q * QPAD + e4 * 4) = v4;
    }
    __syncthreads();

    int k = kbase + warp;
    float krow[EMB];
    const float4* kp = reinterpret_cast<const float4*>(g_k + ((size_t)(b * MCW + k)) * EMB);
#pragma unroll
    for (int i = 0; i < 4; i++) {
        float4 v4 = kp[i];
        krow[4 * i + 0] = v4.x; krow[4 * i + 1] = v4.y;
        krow[4 * i + 2] = v4.z; krow[4 * i + 3] = v4.w;
    }

    float* prow = g_sc + (size_t)b * MCW * MCW + (size_t)k * MCW;
    const float NEG_INF = __int_as_float(0xff800000);

    float v[16];
    bool live[16];
#pragma unroll
    for (int j = 0; j < 16; j++) {
        int q = j * 32 + lane;
        if (j * 32 + 31 < k) {            // chunk entirely masked: prob = 0 exactly
            live[j] = false;
            v[j] = NEG_INF;
            prow[q] = 0.0f;
        } else {
            live[j] = true;
            float dot = 0.f;
#pragma unroll
            for (int e4 = 0; e4 < 4; e4++) {
                float4 a = *reinterpret_cast<const float4*>(sQ + q * QPAD + e4 * 4);
                dot += a.x * krow[4 * e4 + 0] + a.y * krow[4 * e4 + 1]
                     + a.z * krow[4 * e4 + 2] + a.w * krow[4 * e4 + 3];
            }
            float val = (q >= k) ? dot : 0.0f;
            if (val == 0.0f) val = NEG_INF;
            v[j] = val;
        }
    }

    float mx = NEG_INF;
#pragma unroll
    for (int j = 0; j < 16; j++) mx = fmaxf(mx, v[j]);
#pragma unroll
    for (int s = 16; s > 0; s >>= 1) mx = fmaxf(mx, __shfl_xor_sync(0xffffffffu, mx, s));

    float sum = 0.f;
#pragma unroll
    for (int j = 0; j < 16; j++) {
        if (live[j]) { v[j] = expf(v[j] - mx); sum += v[j]; }
    }
#pragma unroll
    for (int s = 16; s > 0; s >>= 1) sum += __shfl_xor_sync(0xffffffffu, sum, s);

    float inv = 1.0f / sum;
#pragma unroll
    for (int j = 0; j < 16; j++) {
        if (live[j]) prow[j * 32 + lane] = v[j] * inv;
    }
}

// ---------------- Kernel C: attnout partials, 8 p-chunks, triangular skip ----------------
__global__ void attnout_kernel() {
    int b = blockIdx.y;
    int w0 = blockIdx.x * 32;
    int c  = blockIdx.z;
    int wl = threadIdx.x, pg = threadIdx.y;

    if (c * CHUNK > w0 + 31) {           // prob exactly 0 here: write zeros, done
        if (pg == 0) {
#pragma unroll
            for (int e = 0; e < EMB; e++)
                g_part[(size_t)c * EMB * NROW + (size_t)e * NROW + b * MCW + w0 + wl] = 0.f;
        }
        return;
    }

    __shared__ float sV[CHUNK * EMB];    // 4 KB
    __shared__ float red[256 * EMB];     // 16 KB
    int tid = pg * 32 + wl;

    for (int i = tid; i < CHUNK * EMB; i += 256)
        sV[i] = g_v[(size_t)b * MCW * EMB + c * CHUNK * EMB + i];
    __syncthreads();

    float acc[EMB];
#pragma unroll
    for (int e = 0; e < EMB; e++) acc[e] = 0.f;

    const float* wbase = g_sc + (size_t)b * MCW * MCW + w0 + wl;
#pragma unroll
    for (int pi = 0; pi < CHUNK / 8; pi++) {
        int pl = pi * 8 + pg;
        float wgt = wbase[(size_t)(c * CHUNK + pl) * MCW];
#pragma unroll
        for (int e = 0; e < EMB; e++) acc[e] += wgt * sV[pl * EMB + e];
    }

#pragma unroll
    for (int e = 0; e < EMB; e++) red[tid * EMB + e] = acc[e];
    __syncthreads();

    if (pg == 0) {
#pragma unroll
        for (int e = 0; e < EMB; e++) {
            float s = 0.f;
#pragma unroll
            for (int g = 0; g < 8; g++) s += red[(g * 32 + wl) * EMB + e];
            g_part[(size_t)c * EMB * NROW + (size_t)e * NROW + b * MCW + w0 + wl] = s;
        }
    }
}

// ---------------- Kernel D: logits = out @ Wl.T + bl  (823 MB write) ----------------
// k=2 vocab/thread @ 128 threads, 4 blocks/SM. Inner loop processes 4 ROWS per
// iteration via LDS.128 (ulonglong2) — halves LDS wavefronts vs LDS.64 (R8's
// L1=73% bottleneck). 4 accumulators: {v0,v1} x {rows01, rows23}.
#define E_RT 128
__global__ __launch_bounds__(128, 4) void logits_kernel(const float* __restrict__ Wl,
                                                        const float* __restrict__ bl,
                                                        float* __restrict__ out) {
    __shared__ __align__(16) float s[EMB * E_RT];   // s[e][r_local], 8 KB
    int tid = threadIdx.x;
    int rbase = blockIdx.y * E_RT;

    // stage s tile = sum of the 8 attnout partial planes (fixed trip count)
    for (int i = tid; i < EMB * E_RT; i += 128) {
        int e = i >> 7, rl = i & (E_RT - 1);
        int idx = e * NROW + rbase + rl;
        float a = 0.f;
#pragma unroll
        for (int c = 0; c < NCHUNK; c++)
            a += g_part[c * (EMB * NROW) + idx];
        s[i] = a;
    }

    int v0 = blockIdx.x * 256 + tid;
    int v1 = v0 + 128;
    bool ok0 = (v0 < VOCAB), ok1 = (v1 < VOCAB);
    ull w0[EMB], w1[EMB], b0 = 0ull, b1 = 0ull;
    if (ok0) {
        const float4* wp = reinterpret_cast<const float4*>(Wl + (size_t)v0 * EMB);
#pragma unroll
        for (int i = 0; i < 4; i++) {
            float4 q = wp[i];
            w0[4 * i + 0] = pack2(q.x, q.x); w0[4 * i + 1] = pack2(q.y, q.y);
            w0[4 * i + 2] = pack2(q.z, q.z); w0[4 * i + 3] = pack2(q.w, q.w);
        }
        float bb = bl[v0]; b0 = pack2(bb, bb);
    } else {
#pragma unroll
        for (int e = 0; e < EMB; e++) w0[e] = 0ull;
    }
    if (ok1) {
        const float4* wp = reinterpret_cast<const float4*>(Wl + (size_t)v1 * EMB);
#pragma unroll
        for (int i = 0; i < 4; i++) {
            float4 q = wp[i];
            w1[4 * i + 0] = pack2(q.x, q.x); w1[4 * i + 1] = pack2(q.y, q.y);
            w1[4 * i + 2] = pack2(q.z, q.z); w1[4 * i + 3] = pack2(q.w, q.w);
        }
        float bb = bl[v1]; b1 = pack2(bb, bb);
    } else {
#pragma unroll
        for (int e = 0; e < EMB; e++) w1[e] = 0ull;
    }
    __syncthreads();

    for (int rpp = 0; rpp < E_RT / 4; rpp++) {      // 4 rows per iteration
        ull a0 = b0, a1 = b1;    // rows (4rpp, 4rpp+1)
        ull c0 = b0, c1 = b1;    // rows (4rpp+2, 4rpp+3)
#pragma unroll
        for (int e = 0; e < EMB; e++) {
            ulonglong2 o2 = *reinterpret_cast<const ulonglong2*>(s + e * E_RT + 4 * rpp);
            asm("fma.rn.f32x2 %0, %1, %2, %0;" : "+l"(a0) : "l"(o2.x), "l"(w0[e]));
            asm("fma.rn.f32x2 %0, %1, %2, %0;" : "+l"(a1) : "l"(o2.x), "l"(w1[e]));
            asm("fma.rn.f32x2 %0, %1, %2, %0;" : "+l"(c0) : "l"(o2.y), "l"(w0[e]));
            asm("fma.rn.f32x2 %0, %1, %2, %0;" : "+l"(c1) : "l"(o2.y), "l"(w1[e]));
        }
        size_t r = (size_t)(rbase + 4 * rpp);
        float lo, hi;
        if (ok0) {
            unpack2(a0, lo, hi);
            __stcs(&out[r * VOCAB + v0], lo);
            __stcs(&out[(r + 1) * VOCAB + v0], hi);
            unpack2(c0, lo, hi);
            __stcs(&out[(r + 2) * VOCAB + v0], lo);
            __stcs(&out[(r + 3) * VOCAB + v0], hi);
        }
        if (ok1) {
            unpack2(a1, lo, hi);
            __stcs(&out[r * VOCAB + v1], lo);
            __stcs(&out[(r + 1) * VOCAB + v1], hi);
            unpack2(c1, lo, hi);
            __stcs(&out[(r + 2) * VOCAB + v1], lo);
            __stcs(&out[(r + 3) * VOCAB + v1], hi);
        }
    }
}

// ---------------- launch ----------------
extern "C" void kernel_launch(void* const* d_in, const int* in_sizes, int n_in,
                              void* d_out, int out_size) {
    const int*   x   = (const int*)  d_in[0];
    const float* emb = (const float*)d_in[1];
    const float* Wq  = (const float*)d_in[2];
    const float* bq  = (const float*)d_in[3];
    const float* Wk  = (const float*)d_in[4];
    const float* bk  = (const float*)d_in[5];
    const float* Wv  = (const float*)d_in[6];
    const float* bv  = (const float*)d_in[7];
    const float* Wl  = (const float*)d_in[8];
    const float* bl  = (const float*)d_in[9];
    float* out = (float*)d_out;

    qkv_kernel<<<NROW / 256, 256>>>(x, emb, Wq, bq, Wk, bk, Wv, bv);

    dim3 gB(MCW / 8, BS);
    scorexmax_kernel<<<gB, 256>>>();

    dim3 gD(MCW / 32, BS, NCHUNK), bD(32, 8);
    attnout_kernel<<<gD, bD>>>();

    dim3 gE((VOCAB + 255) / 256, NROW / E_RT);
    logits_kernel<<<gE, 128>>>(Wl, bl, out);
}